// round 7
// baseline (speedup 1.0000x reference)
#include <cuda_runtime.h>

// Problem shape (fixed):
//   x: (B=4, C2=64, H=256, W=512) fp32 ; D=64 ; C=32
//   out[b,d,h,w] = (1/C) * sum_c L[b,c,h,w] * R[b,c,h,w-d]   (R zero-padded left)
//
// Round-7 design:
//   - CTA = (b, h, w-half), 256 threads, 2048 CTAs, 2 CTAs/SM (72 KB smem each).
//   - Thread tile 8(w) x 8(d): 64 FMAs from 24 smem floats (vs 32 prev round)
//     -> FMA-bound instead of L1TEX-bound.
//   - 32B lane stride would conflict; fixed by XOR swizzle on float4 index:
//     phys_f = f ^ ((f>>3)&1). Applied identically at staging-write and read.
//   - __launch_bounds__(256, 2): 128-reg cap (need ~100), dual residency.

#define CC    32
#define HH    256
#define WW    512
#define DD    64
#define WHALF 256
#define RPADF 64
#define RWID  (WHALF + RPADF)     // 320 floats per R row (80 float4)

#define NTHREADS 256
#define SMEM_BYTES ((CC * WHALF + CC * RWID) * 4)   // 73728

__device__ __forceinline__ int swz(int f) { return f ^ ((f >> 3) & 1); }

__global__ __launch_bounds__(NTHREADS, 2)
void disp_corr_kernel(const float* __restrict__ x, float* __restrict__ out) {
    extern __shared__ float smem[];
    float* Ls = smem;               // [CC][WHALF]  (swizzled float4 within row)
    float* Rs = smem + CC * WHALF;  // [CC][RWID]   (swizzled float4 within row)

    const int bx   = blockIdx.x;         // 0 .. 2*B*H-1
    const int half = bx & 1;
    const int bh   = bx >> 1;
    const int b    = bh >> 8;
    const int h    = bh & 255;
    const int tid  = threadIdx.x;
    const int w_base = half << 8;        // 0 or 256

    const size_t chw = (size_t)HH * WW;
    const float* xL = x + (((size_t)b * 64 + 0 ) * HH + h) * WW;
    const float* xR = x + (((size_t)b * 64 + CC) * HH + h) * WW;

    // ---- Stage L: 32 rows x 64 float4 (coalesced read, swizzled write) ----
    for (int it = tid; it < CC * (WHALF / 4); it += NTHREADS) {
        const int c  = it >> 6;          // /64
        const int w4 = it & 63;          // %64
        float4 v = ((const float4*)(xL + (size_t)c * chw + w_base))[w4];
        ((float4*)(Ls + c * WHALF))[swz(w4)] = v;
    }
    // ---- Stage R: 32 rows x 80 float4, covering s in [w_base-64, w_base+256) ----
    for (int it = tid; it < CC * (RWID / 4); it += NTHREADS) {
        const int c  = it / (RWID / 4);  // /80
        const int i4 = it - c * (RWID / 4);
        const int s4 = (w_base >> 2) - (RPADF / 4) + i4;   // global float4 index
        float4 v = make_float4(0.f, 0.f, 0.f, 0.f);
        if (s4 >= 0) v = ((const float4*)(xR + (size_t)c * chw))[s4];
        ((float4*)(Rs + c * RWID))[swz(i4)] = v;
    }
    __syncthreads();

    // ---- Each thread: 8(w) x 8(d) output tile ----
    // 256 threads * 64 outputs = 16384 = 64 d * 256 w (exact cover)
    const int l   = tid & 31;            // lane
    const int wid = tid >> 5;            // warp 0..7
    const int w0  = l << 3;              // local w, stride 32 B across lanes
    const int d0  = wid << 3;            // d constant per warp
    // R float4 base index: (w0 - d0 + 56)/4 = 2l + 14 - 2*wid, in [0, 76]
    const int rbf = 2 * l + 14 - 2 * wid;

    // Swizzled float4 indices (precomputed; constant over c)
    const int lf0 = swz(2 * l);
    const int lf1 = swz(2 * l + 1);
    const int rf0 = swz(rbf + 0);
    const int rf1 = swz(rbf + 1);
    const int rf2 = swz(rbf + 2);
    const int rf3 = swz(rbf + 3);

    float acc[8][8];

    {   // ---- Channel 0: MUL-init ----
        const float4* lrow = (const float4*)Ls;
        const float4* rrow = (const float4*)Rs;
        const float4 l0 = lrow[lf0], l1 = lrow[lf1];
        const float4 r0 = rrow[rf0], r1 = rrow[rf1], r2 = rrow[rf2], r3 = rrow[rf3];
        const float lv[8]  = { l0.x,l0.y,l0.z,l0.w, l1.x,l1.y,l1.z,l1.w };
        const float rv[16] = { r0.x,r0.y,r0.z,r0.w, r1.x,r1.y,r1.z,r1.w,
                               r2.x,r2.y,r2.z,r2.w, r3.x,r3.y,r3.z,r3.w };
#pragma unroll
        for (int i = 0; i < 8; ++i)
#pragma unroll
            for (int j = 0; j < 8; ++j)
                acc[i][j] = lv[i] * rv[i - j + 8];
    }

    for (int c = 1; c < CC; ++c) {
        const float4* lrow = (const float4*)(Ls + c * WHALF);
        const float4* rrow = (const float4*)(Rs + c * RWID);
        const float4 l0 = lrow[lf0], l1 = lrow[lf1];
        const float4 r0 = rrow[rf0], r1 = rrow[rf1], r2 = rrow[rf2], r3 = rrow[rf3];
        const float lv[8]  = { l0.x,l0.y,l0.z,l0.w, l1.x,l1.y,l1.z,l1.w };
        const float rv[16] = { r0.x,r0.y,r0.z,r0.w, r1.x,r1.y,r1.z,r1.w,
                               r2.x,r2.y,r2.z,r2.w, r3.x,r3.y,r3.z,r3.w };
#pragma unroll
        for (int i = 0; i < 8; ++i)
#pragma unroll
            for (int j = 0; j < 8; ++j)
                // R logical float index: (w0+i) - (d0+j) + 64 = 4*rbf + (i - j + 8)
                acc[i][j] += lv[i] * rv[i - j + 8];
    }

    // ---- Write out[ ((b*D + d)*H + h)*W + w ], two float4 per (thread, j) ----
    const float inv_c = 1.0f / (float)CC;
#pragma unroll
    for (int j = 0; j < 8; ++j) {
        const int d = d0 + j;
        float* row = out + (((size_t)b * DD + d) * HH + h) * WW + w_base + w0;
        ((float4*)row)[0] = make_float4(acc[0][j] * inv_c, acc[1][j] * inv_c,
                                        acc[2][j] * inv_c, acc[3][j] * inv_c);
        ((float4*)row)[1] = make_float4(acc[4][j] * inv_c, acc[5][j] * inv_c,
                                        acc[6][j] * inv_c, acc[7][j] * inv_c);
    }
}

extern "C" void kernel_launch(void* const* d_in, const int* in_sizes, int n_in,
                              void* d_out, int out_size) {
    const float* x = (const float*)d_in[0];
    float* out = (float*)d_out;
    (void)in_sizes; (void)n_in; (void)out_size;

    cudaFuncSetAttribute(disp_corr_kernel,
                         cudaFuncAttributeMaxDynamicSharedMemorySize, SMEM_BYTES);
    disp_corr_kernel<<<2 * 4 * HH, NTHREADS, SMEM_BYTES>>>(x, out);
}

// round 12
// speedup vs baseline: 1.8316x; 1.8316x over previous
#include <cuda_runtime.h>
#include <cstdint>

// DispCorr via SIMT tensor-core mma.sync tf32 (m16n8k8) — base sm_103 features only.
// x: (4, 64, 256, 512) fp32; out[b,d,h,w] = (1/32) sum_c L[c,w] R[c,w-d], d<64.
//
// Per CTA = (b,h). Banded Gram: P[m,n] = sum_k A[m,k] B[n,k]
//   A[m,k] = L[k][w=m]          -> smem [512][36] tf32 (K-major, pad 36)
//   B[n,k] = R[k][s=n-64]       -> smem [576][36] tf32 (rows n<64 zero)
// out[d, m] = P[m, m+64-d]. Each warp+round computes one m16 block with a
// j in [0,80) band: 10 n-tiles x 4 k-steps of m16n8k8 = 40 HMMA, acc in regs.
// Epilogue: fragment scatter -> ob[64][260] (conflict-free) -> float4 STG.

#define A_OFF   0
#define R_OFF   (512 * 36)                    // 18432 floats
#define OB_OFF  (R_OFF + 576 * 36)            // 39168 floats
#define OB_STRIDE 260
#define SMEM_FLOATS (OB_OFF + 64 * OB_STRIDE) // 55808
#define SMEM_BYTES  (SMEM_FLOATS * 4)         // 223232 B

#define CSTR ((size_t)131072)                 // 256*512 (channel stride)

static __device__ __forceinline__ unsigned f2tf32(float f) {
    unsigned u;
    asm("cvt.rna.tf32.f32 %0, %1;" : "=r"(u) : "f"(f));
    return u;
}

static __device__ __forceinline__ void mma16n8k8(float* c, const unsigned* a,
                                                 const unsigned* b) {
    asm volatile(
        "mma.sync.aligned.m16n8k8.row.col.f32.tf32.tf32.f32 "
        "{%0,%1,%2,%3}, {%4,%5,%6,%7}, {%8,%9}, {%0,%1,%2,%3};"
        : "+f"(c[0]), "+f"(c[1]), "+f"(c[2]), "+f"(c[3])
        : "r"(a[0]), "r"(a[1]), "r"(a[2]), "r"(a[3]), "r"(b[0]), "r"(b[1]));
}

__global__ __launch_bounds__(512, 1)
void disp_corr_mma(const float* __restrict__ x, float* __restrict__ out) {
    extern __shared__ unsigned smem_u[];
    float* smem_f = (float*)smem_u;

    const int tid  = threadIdx.x;
    const int warp = tid >> 5;
    const int lane = tid & 31;
    const int gid  = lane >> 2;      // fragment row group
    const int t    = lane & 3;       // fragment col group
    const int b    = blockIdx.x >> 8;
    const int h    = blockIdx.x & 255;

    const float* xL = x + (((size_t)b * 64) * 256 + h) * 512;
    const float* xR = xL + 32 * CSTR;

    // ---- Stage A: row m = tid (coalesced LDG over c, tf32 cvt, STS.128) ----
    {
        unsigned a[32];
        const float* g = xL + tid;
#pragma unroll
        for (int c = 0; c < 32; ++c) a[c] = f2tf32(g[c * CSTR]);
        unsigned* row = smem_u + A_OFF + tid * 36;
#pragma unroll
        for (int q = 0; q < 8; ++q)
            *(uint4*)(row + 4 * q) = make_uint4(a[4*q], a[4*q+1], a[4*q+2], a[4*q+3]);
    }
    // ---- Stage R: rows n = tid, tid+512 ; s = n-64 ; s<0 rows zero ----
    for (int n = tid; n < 576; n += 512) {
        unsigned a[32];
        const int s = n - 64;
        if (s < 0) {
#pragma unroll
            for (int c = 0; c < 32; ++c) a[c] = 0u;
        } else {
            const float* g = xR + s;
#pragma unroll
            for (int c = 0; c < 32; ++c) a[c] = f2tf32(g[c * CSTR]);
        }
        unsigned* row = smem_u + R_OFF + n * 36;
#pragma unroll
        for (int q = 0; q < 8; ++q)
            *(uint4*)(row + 4 * q) = make_uint4(a[4*q], a[4*q+1], a[4*q+2], a[4*q+3]);
    }
    __syncthreads();

    const float inv_c = 1.0f / 32.0f;
    float* ob = smem_f + OB_OFF;

    for (int r = 0; r < 2; ++r) {
        // ---- Compute one m16 block: m0 = 256*r + 16*warp ----
        const int m0 = 256 * r + 16 * warp;
        const int abase = A_OFF + (m0 + gid) * 36 + t;
        const int bbase = R_OFF + (m0 + gid) * 36 + t;   // n0 = m0; +288 per n-tile

        float acc[10][4];
#pragma unroll
        for (int nt = 0; nt < 10; ++nt)
#pragma unroll
            for (int e = 0; e < 4; ++e) acc[nt][e] = 0.f;

#pragma unroll
        for (int ks = 0; ks < 4; ++ks) {
            unsigned a[4];
            a[0] = smem_u[abase + 8 * ks];
            a[1] = smem_u[abase + 288 + 8 * ks];
            a[2] = smem_u[abase + 8 * ks + 4];
            a[3] = smem_u[abase + 288 + 8 * ks + 4];
#pragma unroll
            for (int nt = 0; nt < 10; ++nt) {
                unsigned bb[2];
                bb[0] = smem_u[bbase + nt * 288 + 8 * ks];
                bb[1] = smem_u[bbase + nt * 288 + 8 * ks + 4];
                mma16n8k8(acc[nt], a, bb);
            }
        }

        // ---- Scatter fragments to ob[d][w_loc], d = i - jl + 64 ----
        // i = gid + 8*(reg>>1); jl = 8*nt + 2*t + (reg&1); w_loc = 16*warp + i
#pragma unroll
        for (int nt = 0; nt < 10; ++nt) {
#pragma unroll
            for (int reg = 0; reg < 4; ++reg) {
                const int i  = gid + 8 * (reg >> 1);
                const int jl = 8 * nt + 2 * t + (reg & 1);
                const int d  = i - jl + 64;
                if ((unsigned)d < 64u)
                    ob[d * OB_STRIDE + 16 * warp + i] = acc[nt][reg];
            }
        }
        __syncthreads();

        // ---- Coalesced store: 64 d-rows x 256 w (float4) ----
        for (int it = tid; it < 4096; it += 512) {
            const int d = it >> 6, f4 = it & 63;
            float4 v = *(float4*)(ob + d * OB_STRIDE + 4 * f4);
            v.x *= inv_c; v.y *= inv_c; v.z *= inv_c; v.w *= inv_c;
            *(float4*)(out + (((size_t)b * 64 + d) * 256 + h) * 512 + 256 * r + 4 * f4) = v;
        }
        __syncthreads();
    }
}

extern "C" void kernel_launch(void* const* d_in, const int* in_sizes, int n_in,
                              void* d_out, int out_size) {
    const float* x = (const float*)d_in[0];
    float* out = (float*)d_out;
    (void)in_sizes; (void)n_in; (void)out_size;

    cudaFuncSetAttribute(disp_corr_mma,
                         cudaFuncAttributeMaxDynamicSharedMemorySize, SMEM_BYTES);
    disp_corr_mma<<<1024, 512, SMEM_BYTES>>>(x, out);
}

// round 14
// speedup vs baseline: 2.4928x; 1.3610x over previous
#include <cuda_runtime.h>
#include <cstdint>

// DispCorr via mma.sync tf32 m16n8k8 (base sm_103), round 13 (resubmit):
// quarter-W CTAs + ob aliased over dead operand tiles -> 46 KB smem
// -> 2 CTAs/SM so staging overlaps MMA/epilogue across CTAs.
//
// CTA = (b, h, quarter q): w in [w0, w0+128), all d in [0,64).
//   A[m][k] = tf32(L[k][w0+m])        m in [0,128)   -> smem [128][36]
//   B[n][k] = tf32(R[k][w0-64+n])     n in [0,192)   -> smem [192][36] (s<0 rows zero)
// P[m,n] = sum_k A B ; out[d, w0+m] = P[m, m+64-d] (band jl = n-m0 in [0,80)).
// Warp wm owns m16 block m0 = 16*wm: 10 n-tiles x 4 k-steps = 40 HMMA, acc regs.
// Epilogue: scatter -> ob[64][132] (aliases A/R after sync; conflict-free) -> float4 STG.

#define A_OFF   0
#define R_OFF   (128 * 36)                    // 4608 floats
#define STAGE_FLOATS (R_OFF + 192 * 36)       // 11520 floats = 46080 B
#define OB_STRIDE 132                         // ob[64][132] = 8448 floats (aliased at 0)
#define SMEM_BYTES (STAGE_FLOATS * 4)         // 46080

#define CSTR ((size_t)131072)                 // 256*512 (channel stride)

static __device__ __forceinline__ unsigned f2tf32(float f) {
    unsigned u;
    asm("cvt.rna.tf32.f32 %0, %1;" : "=r"(u) : "f"(f));
    return u;
}

static __device__ __forceinline__ void mma16n8k8(float* c, const unsigned* a,
                                                 const unsigned* b) {
    asm volatile(
        "mma.sync.aligned.m16n8k8.row.col.f32.tf32.tf32.f32 "
        "{%0,%1,%2,%3}, {%4,%5,%6,%7}, {%8,%9}, {%0,%1,%2,%3};"
        : "+f"(c[0]), "+f"(c[1]), "+f"(c[2]), "+f"(c[3])
        : "r"(a[0]), "r"(a[1]), "r"(a[2]), "r"(a[3]), "r"(b[0]), "r"(b[1]));
}

__global__ __launch_bounds__(256, 2)
void disp_corr_mma(const float* __restrict__ x, float* __restrict__ out) {
    extern __shared__ unsigned smem_u[];
    float* smem_f = (float*)smem_u;

    const int tid  = threadIdx.x;
    const int warp = tid >> 5;       // 0..7
    const int lane = tid & 31;
    const int gid  = lane >> 2;      // fragment row group
    const int t    = lane & 3;       // fragment col group
    const int bx   = blockIdx.x;
    const int q    = bx & 3;
    const int bh   = bx >> 2;
    const int b    = bh >> 8;
    const int h    = bh & 255;
    const int w0   = q << 7;         // 0,128,256,384

    const float* xL = x + (((size_t)b * 64) * 256 + h) * 512;
    const float* xR = xL + 32 * CSTR;

    // ---- Stage 320 K-major rows: A m=0..127 (w0+m), R n=0..191 (s=w0-64+n) ----
    for (int it = tid; it < 320; it += 256) {
        unsigned a[32];
        unsigned* row;
        if (it < 128) {
            const float* g = xL + w0 + it;
#pragma unroll
            for (int c = 0; c < 32; ++c) a[c] = f2tf32(g[c * CSTR]);
            row = smem_u + A_OFF + it * 36;
        } else {
            const int n = it - 128;
            const int s = w0 - 64 + n;
            if (s < 0) {
#pragma unroll
                for (int c = 0; c < 32; ++c) a[c] = 0u;
            } else {
                const float* g = xR + s;
#pragma unroll
                for (int c = 0; c < 32; ++c) a[c] = f2tf32(g[c * CSTR]);
            }
            row = smem_u + R_OFF + n * 36;
        }
#pragma unroll
        for (int qq = 0; qq < 8; ++qq)
            *(uint4*)(row + 4 * qq) = make_uint4(a[4*qq], a[4*qq+1], a[4*qq+2], a[4*qq+3]);
    }
    __syncthreads();

    // ---- Compute: warp's m16 block m0 = 16*warp; band jl in [0,80) ----
    const int m0 = 16 * warp;
    const int abase = A_OFF + (m0 + gid) * 36 + t;
    const int bbase = R_OFF + (m0 + gid) * 36 + t;   // n = m0 + 8*nt + gid via +288*nt

    float acc[10][4];
#pragma unroll
    for (int nt = 0; nt < 10; ++nt)
#pragma unroll
        for (int e = 0; e < 4; ++e) acc[nt][e] = 0.f;

#pragma unroll
    for (int ks = 0; ks < 4; ++ks) {
        unsigned a[4];
        a[0] = smem_u[abase + 8 * ks];
        a[1] = smem_u[abase + 288 + 8 * ks];
        a[2] = smem_u[abase + 8 * ks + 4];
        a[3] = smem_u[abase + 288 + 8 * ks + 4];
#pragma unroll
        for (int nt = 0; nt < 10; ++nt) {
            unsigned bb[2];
            bb[0] = smem_u[bbase + nt * 288 + 8 * ks];
            bb[1] = smem_u[bbase + nt * 288 + 8 * ks + 4];
            mma16n8k8(acc[nt], a, bb);
        }
    }
    __syncthreads();   // operand tiles dead; ob aliases them

    // ---- Scatter fragments to ob[d][w_loc], d = i - jl + 64 ----
    // i = gid + 8*(reg>>1); jl = 8*nt + 2*t + (reg&1); w_loc = 16*warp + i
    float* ob = smem_f;
#pragma unroll
    for (int nt = 0; nt < 10; ++nt) {
#pragma unroll
        for (int reg = 0; reg < 4; ++reg) {
            const int i  = gid + 8 * (reg >> 1);
            const int jl = 8 * nt + 2 * t + (reg & 1);
            const int d  = i - jl + 64;
            if ((unsigned)d < 64u)
                ob[d * OB_STRIDE + m0 + i] = acc[nt][reg];
        }
    }
    __syncthreads();

    // ---- Coalesced store: 64 d-rows x 128 w (float4) ----
    const float inv_c = 1.0f / 32.0f;
    for (int it = tid; it < 2048; it += 256) {
        const int d = it >> 5, f4 = it & 31;
        float4 v = *(float4*)(ob + d * OB_STRIDE + 4 * f4);
        v.x *= inv_c; v.y *= inv_c; v.z *= inv_c; v.w *= inv_c;
        *(float4*)(out + (((size_t)b * 64 + d) * 256 + h) * 512 + w0 + 4 * f4) = v;
    }
}

extern "C" void kernel_launch(void* const* d_in, const int* in_sizes, int n_in,
                              void* d_out, int out_size) {
    const float* x = (const float*)d_in[0];
    float* out = (float*)d_out;
    (void)in_sizes; (void)n_in; (void)out_size;

    cudaFuncSetAttribute(disp_corr_mma,
                         cudaFuncAttributeMaxDynamicSharedMemorySize, SMEM_BYTES);
    disp_corr_mma<<<4096, 256, SMEM_BYTES>>>(x, out);
}